// round 1
// baseline (speedup 1.0000x reference)
#include <cuda_runtime.h>

namespace {

constexpr int T_ = 128, H_ = 16, N_ = 64, C_ = 256, S_ = 129;
constexpr int HNC = H_ * N_ * C_;   // 262144
constexpr int NC_ = N_ * C_;        // 16384
constexpr int HN_ = H_ * N_;        // 1024

__device__ __forceinline__ float log_add_f(float a, float b) {
    float x = fmaxf(a, b);
    float y = fminf(a, b);
    return x + log1pf(expf(y - x));
}

__global__ __launch_bounds__(544, 1) void ctc2d_kernel(
    const float* __restrict__ mask,      // [T,H,N]
    const float* __restrict__ classify,  // [T,H,N,C]
    const int*   __restrict__ targets,   // [N,64]
    const int*   __restrict__ tlen,      // [N]
    float* __restrict__ out)             // [N]
{
    constexpr float  TINYF     = 1.1754943508222875e-38f;
    constexpr float  LOG_TINYF = -87.33654475055310898f;
    constexpr float  P0R       = -90.10913347279289f;       // LOG_TINY - log(16)
    constexpr double EXP_M88   = 6.054601895401186e-39;     // exp(-88) in double

    __shared__ float hs_sh[S_];
    __shared__ float np_sh[S_];
    __shared__ int   et_sh[S_];
    __shared__ int   skip_sh[S_];
    __shared__ int   cc_sh[T_];
    __shared__ float x_sh[S_ * H_];

    const int  n    = blockIdx.x;
    const int  tid  = threadIdx.x;
    const bool act  = tid < 4 * S_;                 // 516 active threads
    const int  sA   = act ? (tid >> 2) : 0;        // state index
    const int  h0   = (tid & 3) * 4;               // this thread's first head

    // expanded-with-blank targets: et[s] = blank(0) for even s, targets[(s-1)/2] for odd s
    if (tid < S_) et_sh[tid] = (tid & 1) ? targets[n * 64 + (tid >> 1)] : 0;
    __syncthreads();
    if (tid < S_) {
        skip_sh[tid] = (tid >= 2) ? ((et_sh[tid] != et_sh[tid - 2]) ? 1 : 0) : 0;
        np_sh[tid]   = (tid < 2) ? 0.0f : P0R;     // p0 encoded as newp(+cls) form
    }
    __syncthreads();
    // cc cumsum for reachability frontier: rows [msf0+1, msf0+1, msf0+1, msf1+1, ...]
    if (tid == 0) {
        int c = 2 * (skip_sh[2] + 1);
        cc_sh[1] = c;
        for (int t = 2; t < T_; ++t) { c += skip_sh[t] + 1; cc_sh[t] = c; }
    }
    __syncthreads();

    // Static gather addresses (only t-stride varies) -> full prefetch pipeline.
    const int    etv   = et_sh[sA];
    const float* cbase = classify + (size_t)n * C_ + etv;
    const float* mbase = mask + n;
    int coff[4], moff[4];
#pragma unroll
    for (int j = 0; j < 4; ++j) { coff[j] = (h0 + j) * NC_; moff[j] = (h0 + j) * N_; }

    float cls_n[4], m_n[4];
#pragma unroll
    for (int j = 0; j < 4; ++j) {
        cls_n[j] = __ldg(cbase + coff[j]);   // classify[0]
        m_n[j]   = __ldg(mbase + moff[j]);   // mask[0]
    }

    for (int t = 1; t < T_; ++t) {
        float cls_c[4], m_c[4];
#pragma unroll
        for (int j = 0; j < 4; ++j) { cls_c[j] = cls_n[j]; m_c[j] = m_n[j]; }
        // prefetch operands for step t+1 (classify[t], mask[t]); last iter -> final stage
        const float* cpt = cbase + (size_t)t * HNC;
        const float* mpt = mbase + t * HN_;
#pragma unroll
        for (int j = 0; j < 4; ++j) {
            cls_n[j] = __ldg(cpt + coff[j]);
            m_n[j]   = __ldg(mpt + moff[j]);
        }
        // first step: p0 for s>=2 is the constant P0R, i.e. cls contribution = 0
        if (t == 1 && sA >= 2) {
#pragma unroll
            for (int j = 0; j < 4; ++j) cls_c[j] = 0.0f;
        }

        const float nv = np_sh[sA];
        // sum_h exp( (newp + cls) + m )  -- double accumulation so subnormal
        // contributions survive regardless of FTZ compile flags; deep-underflow
        // exp via shift to mirror reference float32 subnormal behavior.
        double sd = 0.0;
#pragma unroll
        for (int j = 0; j < 4; ++j) {
            float x = (nv + cls_c[j]) + m_c[j];
            if (x < -60.0f) sd += (double)expf(x + 88.0f) * EXP_M88;
            else            sd += (double)expf(x);
        }
        sd += __shfl_xor_sync(0xffffffffu, sd, 1);
        sd += __shfl_xor_sync(0xffffffffu, sd, 2);

        if (act && (tid & 3) == 0) {
            float sf = fmaxf((float)sd, TINYF);     // log(max(sum, TINY))
            float v  = logf(sf);
            if (sA > cc_sh[t]) v = LOG_TINYF;       // unreachable-state floor
            hs_sh[sA] = v;
        }
        __syncthreads();

        // transitions (elementwise in s, parallel)
        if (tid < S_) {
            float v;
            if (tid == 0) {
                v = hs_sh[0];
            } else {
                v = log_add_f(hs_sh[tid], hs_sh[tid - 1]);
                if (tid >= 2 && skip_sh[tid]) v = log_add_f(v, hs_sh[tid - 2]);
            }
            np_sh[tid] = v;
        }
        __syncthreads();
    }

    // Final: x = (newp + classify[127]) + mask[127]; sequential log_add fold over h
    if (act) {
        const float nv = np_sh[sA];
#pragma unroll
        for (int j = 0; j < 4; ++j)
            x_sh[sA * H_ + h0 + j] = (nv + cls_n[j]) + m_n[j];
    }
    __syncthreads();
    if (tid < S_) {
        float r = x_sh[tid * H_];
#pragma unroll
        for (int h = 1; h < H_; ++h) r = log_add_f(r, x_sh[tid * H_ + h]);
        np_sh[tid] = r;
    }
    __syncthreads();
    if (tid == 0) {
        int   L    = 2 * tlen[n] + 1;
        float loss = log_add_f(np_sh[L - 1], np_sh[L - 2]);
        out[n] = -(loss / (float)tlen[n]);
    }
}

} // anonymous namespace

extern "C" void kernel_launch(void* const* d_in, const int* /*in_sizes*/, int /*n_in*/,
                              void* d_out, int /*out_size*/) {
    const float* mask     = (const float*)d_in[0];
    const float* classify = (const float*)d_in[1];
    const int*   targets  = (const int*)d_in[2];
    // d_in[3] = input_lengths (unused: always T)
    const int*   tlen     = (const int*)d_in[4];
    ctc2d_kernel<<<N_, 544>>>(mask, classify, targets, tlen, (float*)d_out);
}

// round 2
// speedup vs baseline: 3.8354x; 3.8354x over previous
#include <cuda_runtime.h>

namespace {

constexpr int T_ = 128, H_ = 16, N_ = 64, C_ = 256, S_ = 129;
constexpr int NC_ = N_ * C_;
constexpr int SPAD = 132;   // padded S for float4 alignment

constexpr float LOG_TINYF = -87.33654475055310898f;

__device__ float G_buf[T_][N_][SPAD];   // 4.3 MB scratch

__device__ __forceinline__ float log_add_f(float a, float b) {
    float x = fmaxf(a, b);
    float y = fminf(a, b);
    return x + log1pf(expf(y - x));
}

// ---------------------------------------------------------------------------
// Kernel 1: G[t][n][s] = log( sum_h exp( classify[t,h,n,et[s]] + mask[t,h,n] ) )
// Dedupe over states: even s -> blank column 0; odd s -> targets[(s-1)/2].
// 65 distinct columns x 16 heads, 4 heads/thread, quad shuffle-reduce.
// ---------------------------------------------------------------------------
__global__ __launch_bounds__(288) void g_kernel(
    const float* __restrict__ mask,      // [T,H,N]
    const float* __restrict__ classify,  // [T,H,N,C]
    const int*   __restrict__ targets)   // [N,64]
{
    const int t = blockIdx.x, n = blockIdx.y, tid = threadIdx.x;

    __shared__ float m_sh[H_];
    __shared__ float S_sh[65];

    if (tid < H_) m_sh[tid] = mask[(t * H_ + tid) * N_ + n];
    __syncthreads();

    {
        int c = tid >> 2;
        if (c > 64) c = 64;                      // clamp tail threads (benign dup)
        const int h0  = (tid & 3) * 4;
        const int col = (c == 0) ? 0 : __ldg(&targets[n * 64 + c - 1]);
        const float* base = classify + ((size_t)(t * H_ + h0) * N_ + n) * C_ + col;
        float s0 = 0.f;
#pragma unroll
        for (int j = 0; j < 4; ++j)
            s0 += expf(__ldg(base + (size_t)j * NC_) + m_sh[h0 + j]);
        s0 += __shfl_xor_sync(0xffffffffu, s0, 1);
        s0 += __shfl_xor_sync(0xffffffffu, s0, 2);
        if ((tid & 3) == 0) S_sh[c] = s0;        // duplicate c=64 writes are same value
    }
    __syncthreads();

    if (tid < S_) {
        float S = S_sh[(tid & 1) ? (1 + (tid >> 1)) : 0];
        G_buf[t][n][tid] = logf(S);
    }
}

// ---------------------------------------------------------------------------
// Kernel 2: the CTC recurrence, one warp per batch item, all in registers.
//   hs[s] = max(np[s] + G[t-1][s], LOG_TINY); floor where s > cc[t]
//   np[s] = log_add(hs[s], hs[s-1]) (+ hs[s-2] if skip[s])
// Lane l owns states 4l..4l+3 (lane 31 also owns s=128).
// ---------------------------------------------------------------------------
__global__ __launch_bounds__(32) void rec_kernel(
    const int* __restrict__ targets,   // [N,64]
    const int* __restrict__ tlen,      // [N]
    float* __restrict__ out)           // [N]
{
    const int n    = blockIdx.x;
    const int lane = threadIdx.x;
    const int NS   = (lane == 31) ? 5 : 4;
    const int sB   = 4 * lane;

    __shared__ int   cc_sh[T_];
    __shared__ int   tgt_sh[64];
    __shared__ float res_sh[S_];

    tgt_sh[lane]      = targets[n * 64 + lane];
    tgt_sh[lane + 32] = targets[n * 64 + lane + 32];
    __syncwarp();

    if (lane == 0) {
        int c = 2;
        cc_sh[1] = 2;                      // skip[2] = 0 (even state), so cc[1]=2
        for (int t = 2; t < T_; ++t) {
            int sk = 0;
            if ((t & 1) && t >= 3) sk = (tgt_sh[(t - 1) >> 1] != tgt_sh[(t - 3) >> 1]);
            c += sk + 1;
            cc_sh[t] = c;
        }
    }
    __syncwarp();

    // skip bits for owned states (only odd s >= 3 can skip)
    bool skipb[5];
#pragma unroll
    for (int i = 0; i < 5; ++i) {
        int s = sB + i;
        skipb[i] = (i < NS) && (s & 1) && (s >= 3) &&
                   (tgt_sh[(s - 1) >> 1] != tgt_sh[(s - 3) >> 1]);
    }

    // np encodes the incoming log-prob without the cls/mask term.
    // t=1 initial state: np=0 for s<2; s>=2 starts at hard floor (p0 const path).
    float np[5], g[5];
#pragma unroll
    for (int i = 0; i < 5; ++i) np[i] = (sB + i < 2) ? 0.f : -1e30f;

    {   // load G[0]
        const float* G0 = &G_buf[0][n][0];
        float4 v = *reinterpret_cast<const float4*>(G0 + sB);
        g[0] = v.x; g[1] = v.y; g[2] = v.z; g[3] = v.w;
        g[4] = (lane == 31) ? G0[sB + 4] : 0.f;
    }
    int cc_t = cc_sh[1];

    for (int t = 1; t < T_; ++t) {
        // prefetch G[t] (used next iter; at t=127 it is the final-stage G)
        float gn[5];
        {
            const float* Gp = &G_buf[t][n][0];
            float4 v = *reinterpret_cast<const float4*>(Gp + sB);
            gn[0] = v.x; gn[1] = v.y; gn[2] = v.z; gn[3] = v.w;
            gn[4] = (lane == 31) ? Gp[sB + 4] : 0.f;
        }
        const int cc_next = (t + 1 < T_) ? cc_sh[t + 1] : 0;

        float hs[5];
#pragma unroll
        for (int i = 0; i < 5; ++i) {
            float h = fmaxf(np[i] + g[i], LOG_TINYF);
            if (sB + i > cc_t) h = LOG_TINYF;
            hs[i] = h;
        }

        // neighbor states from lane-1: its hs[3] = hs[sB-1], hs[2] = hs[sB-2]
        const float hm1 = __shfl_up_sync(0xffffffffu, hs[3], 1);
        const float hm2 = __shfl_up_sync(0xffffffffu, hs[2], 1);

        float npn[5];
        if (lane == 0) {
            npn[0] = hs[0];                               // s=0: np = hs[0]
        } else {
            float a = log_add_f(hs[0], hm1);
            if (skipb[0]) a = log_add_f(a, hm2);
            npn[0] = a;
        }
        {
            float a = log_add_f(hs[1], hs[0]);            // s=1 (lane0) has no skip
            if (skipb[1]) a = log_add_f(a, hm1);
            npn[1] = a;
        }
#pragma unroll
        for (int i = 2; i < 5; ++i) {
            float a = log_add_f(hs[i], hs[i - 1]);
            if (skipb[i]) a = log_add_f(a, hs[i - 2]);
            npn[i] = a;
        }

#pragma unroll
        for (int i = 0; i < 5; ++i) { np[i] = npn[i]; g[i] = gn[i]; }
        cc_t = cc_next;
    }

    // final: res[s] = np[s] + G[127][s]  (factored logsumexp over h)
#pragma unroll
    for (int i = 0; i < 5; ++i)
        if (i < NS) res_sh[sB + i] = np[i] + g[i];
    __syncwarp();

    if (lane == 0) {
        const int   L    = 2 * tlen[n] + 1;
        const float loss = log_add_f(res_sh[L - 1], res_sh[L - 2]);
        out[n] = -(loss / (float)tlen[n]);
    }
}

} // anonymous namespace

extern "C" void kernel_launch(void* const* d_in, const int* /*in_sizes*/, int /*n_in*/,
                              void* d_out, int /*out_size*/) {
    const float* mask     = (const float*)d_in[0];
    const float* classify = (const float*)d_in[1];
    const int*   targets  = (const int*)d_in[2];
    // d_in[3] = input_lengths (always T, unused)
    const int*   tlen     = (const int*)d_in[4];

    g_kernel<<<dim3(T_, N_), 288>>>(mask, classify, targets);
    rec_kernel<<<N_, 32>>>(targets, tlen, (float*)d_out);
}

// round 3
// speedup vs baseline: 4.0190x; 1.0479x over previous
#include <cuda_runtime.h>

namespace {

constexpr int T_ = 128, H_ = 16, N_ = 64, C_ = 256, S_ = 129;
constexpr int NC_ = N_ * C_;
constexpr int SPAD = 132;   // padded S for float4 alignment

constexpr float LOG_TINYF = -87.33654475055310898f;
constexpr float NEG_BIG   = -1e30f;

__device__ float G_buf[T_][N_][SPAD];   // 4.3 MB scratch

// fast 3-way logsumexp (MUFU-based); a,b finite >= -1e30, c may be -1e30 (drops out)
__device__ __forceinline__ float lse3(float a, float b, float c) {
    float m = fmaxf(fmaxf(a, b), c);
    float s = __expf(a - m) + __expf(b - m) + __expf(c - m);
    return m + __logf(s);
}
__device__ __forceinline__ float lse2(float a, float b) {
    float m = fmaxf(a, b);
    float d = fminf(a, b) - m;
    return m + __logf(1.f + __expf(d));
}

// ---------------------------------------------------------------------------
// Kernel 1: G[t][n][s] = log( sum_h exp( classify[t,h,n,et[s]] + mask[t,h,n] ) )
// Dedupe: even s -> blank col 0; odd s -> targets[(s-1)/2]. 65 cols x 16 heads,
// 4 heads/thread, quad shuffle-reduce. Memory-sector bound.
// ---------------------------------------------------------------------------
__global__ __launch_bounds__(288) void g_kernel(
    const float* __restrict__ mask,      // [T,H,N]
    const float* __restrict__ classify,  // [T,H,N,C]
    const int*   __restrict__ targets)   // [N,64]
{
    const int t = blockIdx.x, n = blockIdx.y, tid = threadIdx.x;

    __shared__ float m_sh[H_];
    __shared__ float S_sh[65];

    if (tid < H_) m_sh[tid] = mask[(t * H_ + tid) * N_ + n];
    __syncthreads();

    {
        int c = tid >> 2;
        if (c > 64) c = 64;                      // clamp tail threads (benign dup)
        const int h0  = (tid & 3) * 4;
        const int col = (c == 0) ? 0 : __ldg(&targets[n * 64 + c - 1]);
        const float* base = classify + ((size_t)(t * H_ + h0) * N_ + n) * C_ + col;
        float v0 = __ldg(base);
        float v1 = __ldg(base + (size_t)NC_);
        float v2 = __ldg(base + (size_t)2 * NC_);
        float v3 = __ldg(base + (size_t)3 * NC_);
        float s0 = __expf(v0 + m_sh[h0]) + __expf(v1 + m_sh[h0 + 1]) +
                   __expf(v2 + m_sh[h0 + 2]) + __expf(v3 + m_sh[h0 + 3]);
        s0 += __shfl_xor_sync(0xffffffffu, s0, 1);
        s0 += __shfl_xor_sync(0xffffffffu, s0, 2);
        if ((tid & 3) == 0) S_sh[c] = s0;
    }
    __syncthreads();

    if (tid < S_) {
        float S = S_sh[(tid & 1) ? (1 + (tid >> 1)) : 0];
        G_buf[t][n][tid] = __logf(S);
    }
}

// ---------------------------------------------------------------------------
// Kernel 2: CTC recurrence, one warp per batch item, all in registers.
//   hs[s] = max(np[s] + G[t-1][s], LOG_TINY); floored where s > cc[t]
//   np[s] = lse(hs[s], hs[s-1] [, hs[s-2] if skip])
// Lane l owns states 4l..4l+3 (lane 31 also owns s=128).
// ---------------------------------------------------------------------------
__global__ __launch_bounds__(32) void rec_kernel(
    const int* __restrict__ targets,   // [N,64]
    const int* __restrict__ tlen,      // [N]
    float* __restrict__ out)           // [N]
{
    const int n    = blockIdx.x;
    const int lane = threadIdx.x;
    const int NS   = (lane == 31) ? 5 : 4;
    const int sB   = 4 * lane;

    __shared__ int   cc_sh[T_];
    __shared__ int   tgt_sh[64];
    __shared__ float res_sh[S_];

    tgt_sh[lane]      = targets[n * 64 + lane];
    tgt_sh[lane + 32] = targets[n * 64 + lane + 32];
    __syncwarp();

    // cc[t] = 2 + sum_{u=2..t} (sk(u)+1), cc[1] = 2 -> warp-parallel prefix scan.
    {
        int c[4], p = 0;
#pragma unroll
        for (int i = 0; i < 4; ++i) {
            int u = 4 * lane + i;
            int v = 0;
            if (u >= 2) {
                int sk = 0;
                if ((u & 1) && u >= 3) sk = (tgt_sh[(u - 1) >> 1] != tgt_sh[(u - 3) >> 1]);
                v = sk + 1;
            }
            p += v;
            c[i] = p;   // inclusive local prefix
        }
        int tot = p;
#pragma unroll
        for (int d = 1; d < 32; d <<= 1) {
            int up = __shfl_up_sync(0xffffffffu, tot, d);
            if (lane >= d) tot += up;
        }
        int excl = tot - p;
#pragma unroll
        for (int i = 0; i < 4; ++i) {
            int u = 4 * lane + i;
            if (u >= 1) cc_sh[u] = 2 + excl + c[i];
        }
    }
    __syncwarp();

    // skip bits for owned states (only odd s >= 3 can skip)
    bool skipb[5];
#pragma unroll
    for (int i = 0; i < 5; ++i) {
        int s = sB + i;
        skipb[i] = (i < NS) && (s & 1) && (s >= 3) &&
                   (tgt_sh[(s - 1) >> 1] != tgt_sh[(s - 3) >> 1]);
    }

    float np[5], g[5];
#pragma unroll
    for (int i = 0; i < 5; ++i) np[i] = (sB + i < 2) ? 0.f : NEG_BIG;

    {   // load G[0]
        const float* G0 = &G_buf[0][n][0];
        float4 v = *reinterpret_cast<const float4*>(G0 + sB);
        g[0] = v.x; g[1] = v.y; g[2] = v.z; g[3] = v.w;
        g[4] = (lane == 31) ? G0[sB + 4] : 0.f;
    }
    int cc_t = cc_sh[1];

    for (int t = 1; t < T_; ++t) {
        // prefetch G[t] (used next iter; at t=127 it's the final-stage G)
        float gn[5];
        {
            const float* Gp = &G_buf[t][n][0];
            float4 v = *reinterpret_cast<const float4*>(Gp + sB);
            gn[0] = v.x; gn[1] = v.y; gn[2] = v.z; gn[3] = v.w;
            gn[4] = (lane == 31) ? Gp[sB + 4] : 0.f;
        }
        const int cc_next = (t + 1 < T_) ? cc_sh[t + 1] : 0;

        float hs[5];
#pragma unroll
        for (int i = 0; i < 5; ++i) {
            float h = fmaxf(np[i] + g[i], LOG_TINYF);
            if (sB + i > cc_t) h = LOG_TINYF;
            hs[i] = h;
        }

        // neighbors from lane-1: its hs[3] = hs[sB-1], hs[2] = hs[sB-2]
        const float hm1 = __shfl_up_sync(0xffffffffu, hs[3], 1);
        const float hm2 = __shfl_up_sync(0xffffffffu, hs[2], 1);

        float npn[5];
        npn[0] = (lane == 0) ? hs[0]
                             : lse3(hs[0], hm1, skipb[0] ? hm2 : NEG_BIG);
        npn[1] = lse3(hs[1], hs[0], skipb[1] ? hm1 : NEG_BIG);
#pragma unroll
        for (int i = 2; i < 5; ++i)
            npn[i] = lse3(hs[i], hs[i - 1], skipb[i] ? hs[i - 2] : NEG_BIG);

#pragma unroll
        for (int i = 0; i < 5; ++i) { np[i] = npn[i]; g[i] = gn[i]; }
        cc_t = cc_next;
    }

    // final: res[s] = np[s] + G[127][s]
#pragma unroll
    for (int i = 0; i < 5; ++i)
        if (i < NS) res_sh[sB + i] = np[i] + g[i];
    __syncwarp();

    if (lane == 0) {
        const int   L    = 2 * tlen[n] + 1;
        const float loss = lse2(res_sh[L - 1], res_sh[L - 2]);
        out[n] = -(loss / (float)tlen[n]);
    }
}

} // anonymous namespace

extern "C" void kernel_launch(void* const* d_in, const int* /*in_sizes*/, int /*n_in*/,
                              void* d_out, int /*out_size*/) {
    const float* mask     = (const float*)d_in[0];
    const float* classify = (const float*)d_in[1];
    const int*   targets  = (const int*)d_in[2];
    // d_in[3] = input_lengths (always T, unused)
    const int*   tlen     = (const int*)d_in[4];

    g_kernel<<<dim3(T_, N_), 288>>>(mask, classify, targets);
    rec_kernel<<<N_, 32>>>(targets, tlen, (float*)d_out);
}

// round 4
// speedup vs baseline: 7.0184x; 1.7463x over previous
#include <cuda_runtime.h>

namespace {

constexpr int T_ = 128, H_ = 16, N_ = 64, C_ = 256, S_ = 129;
constexpr int NPROD = 15;          // producer warps; warp 15 = consumer
constexpr int CPAD  = 68;          // padded 65 columns

constexpr float L2E     = 1.4426950408889634f;   // log2(e)
constexpr float LN2     = 0.6931471805599453f;
constexpr float FLOOR2  = -126.0f;               // log2(FLT_MIN) == LOG_TINY/ln2
constexpr float NEG_BIG = -1e30f;

__device__ __forceinline__ float ex2f(float x) { float y; asm("ex2.approx.f32 %0, %1;" : "=f"(y) : "f"(x)); return y; }
__device__ __forceinline__ float lg2f(float x) { float y; asm("lg2.approx.f32 %0, %1;" : "=f"(y) : "f"(x)); return y; }

// 3-way logsumexp in base-2; c may be NEG_BIG (its ex2 underflows to 0)
__device__ __forceinline__ float lse3_2(float a, float b, float c) {
    float m = fmaxf(fmaxf(a, b), c);
    float s = ex2f(a - m) + ex2f(b - m) + ex2f(c - m);
    return m + lg2f(s);
}

__global__ __launch_bounds__(512, 1) void fused_kernel(
    const float* __restrict__ mask,      // [T,H,N]
    const float* __restrict__ classify,  // [T,H,N,C]
    const int*   __restrict__ targets,   // [N,64]
    const int*   __restrict__ tlen,      // [N]
    float* __restrict__ out)             // [N]
{
    __shared__ float G2[T_][CPAD];   // per-column log2-sums, row t
    __shared__ float m_sh[T_ * H_];
    __shared__ int   flag[T_];
    __shared__ int   tgt_sh[64];
    __shared__ float res_sh[S_];

    const int n    = blockIdx.x;
    const int tid  = threadIdx.x;
    const int w    = tid >> 5;
    const int lane = tid & 31;

    for (int i = tid; i < T_ * H_; i += 512) m_sh[i] = mask[i * N_ + n];
    if (tid < T_) flag[tid] = 0;
    if (tid < 64) tgt_sh[tid] = targets[n * 64 + tid];
    __syncthreads();

    if (w < NPROD) {
        // ----------------- producers: rows t = w, w+15, ... -----------------
        // lane handles cols c1=lane, c2=32+lane; lane 31 additionally c=64.
        const int c1 = lane, c2 = 32 + lane;
        const int col1 = (c1 == 0) ? 0 : tgt_sh[c1 - 1];
        const int col2 = tgt_sh[c2 - 1];
        const int col3 = tgt_sh[63];
        const size_t b1 = (size_t)n * C_ + col1;
        const size_t b2 = (size_t)n * C_ + col2;
        const size_t b3 = (size_t)n * C_ + col3;
        const bool   l31 = (lane == 31);

        for (int t = w; t < T_; t += NPROD) {
            const float* base = classify + (size_t)t * H_ * N_ * C_;
            const float* mrow = m_sh + t * H_;
            float v1[H_], v2[H_], v3[H_];
#pragma unroll
            for (int h = 0; h < H_; ++h) {
                const size_t ho = (size_t)h * N_ * C_;
                v1[h] = __ldg(base + ho + b1);
                v2[h] = __ldg(base + ho + b2);
            }
            if (l31) {
#pragma unroll
                for (int h = 0; h < H_; ++h) v3[h] = __ldg(base + (size_t)h * N_ * C_ + b3);
            }
            float s1 = 0.f, s2 = 0.f;
#pragma unroll
            for (int h = 0; h < H_; ++h) {
                const float mh = mrow[h];
                s1 += ex2f((v1[h] + mh) * L2E);
                s2 += ex2f((v2[h] + mh) * L2E);
            }
            G2[t][c1] = lg2f(s1);
            G2[t][c2] = lg2f(s2);
            if (l31) {
                float s3 = 0.f;
#pragma unroll
                for (int h = 0; h < H_; ++h) s3 += ex2f((v3[h] + mrow[h]) * L2E);
                G2[t][64] = lg2f(s3);
            }
            __syncwarp();
            __threadfence_block();                       // release
            if (lane == 0) *(volatile int*)&flag[t] = 1;
        }
    } else {
        // ----------------- consumer: serial CTC recurrence ------------------
        __shared__ int cc_sh[T_];
        const int NS = (lane == 31) ? 5 : 4;
        const int sB = 4 * lane;

        // cc prefix scan (reachability frontier)
        {
            int c[4], p = 0;
#pragma unroll
            for (int i = 0; i < 4; ++i) {
                int u = 4 * lane + i, v = 0;
                if (u >= 2) {
                    int sk = 0;
                    if ((u & 1) && u >= 3) sk = (tgt_sh[(u - 1) >> 1] != tgt_sh[(u - 3) >> 1]);
                    v = sk + 1;
                }
                p += v; c[i] = p;
            }
            int tot = p;
#pragma unroll
            for (int d = 1; d < 32; d <<= 1) {
                int up = __shfl_up_sync(0xffffffffu, tot, d);
                if (lane >= d) tot += up;
            }
            int excl = tot - p;
#pragma unroll
            for (int i = 0; i < 4; ++i) {
                int u = 4 * lane + i;
                if (u >= 1) cc_sh[u] = 2 + excl + c[i];
            }
        }
        __syncwarp();

        bool skipb[5];
#pragma unroll
        for (int i = 0; i < 5; ++i) {
            int s = sB + i;
            skipb[i] = (i < NS) && (s & 1) && (s >= 3) &&
                       (tgt_sh[(s - 1) >> 1] != tgt_sh[(s - 3) >> 1]);
        }

        // column indices for owned states: even -> 0, odd s -> (s+1)/2
        const int cOdd1 = 2 * lane + 1;   // state 4l+1
        const int cOdd2 = 2 * lane + 2;   // state 4l+3

        float np[5];
#pragma unroll
        for (int i = 0; i < 5; ++i) np[i] = (sB + i < 2) ? 0.f : NEG_BIG;

        // wait for & load row 0
        while (*(volatile int*)&flag[0] == 0) {}
        __syncwarp();
        __threadfence_block();                           // acquire
        float gE = G2[0][0], gO1 = G2[0][cOdd1], gO2 = G2[0][cOdd2];

        for (int t = 1; t < T_; ++t) {
            while (*(volatile int*)&flag[t] == 0) {}
            __syncwarp();
            __threadfence_block();
            // issue next-row LDS early; consumed after this step's math
            const float gEn = G2[t][0], gO1n = G2[t][cOdd1], gO2n = G2[t][cOdd2];
            const int cc_t = cc_sh[t];

            float hs[5];
            hs[0] = fmaxf(np[0] + gE,  FLOOR2);
            hs[1] = fmaxf(np[1] + gO1, FLOOR2);
            hs[2] = fmaxf(np[2] + gE,  FLOOR2);
            hs[3] = fmaxf(np[3] + gO2, FLOOR2);
            hs[4] = fmaxf(np[4] + gE,  FLOOR2);
#pragma unroll
            for (int i = 0; i < 5; ++i)
                if (sB + i > cc_t) hs[i] = FLOOR2;

            const float hm1 = __shfl_up_sync(0xffffffffu, hs[3], 1);
            const float hm2 = __shfl_up_sync(0xffffffffu, hs[2], 1);

            float npn[5];
            npn[0] = (lane == 0) ? hs[0]
                                 : lse3_2(hs[0], hm1, skipb[0] ? hm2 : NEG_BIG);
            npn[1] = lse3_2(hs[1], hs[0], skipb[1] ? hm1 : NEG_BIG);
#pragma unroll
            for (int i = 2; i < 5; ++i)
                npn[i] = lse3_2(hs[i], hs[i - 1], skipb[i] ? hs[i - 2] : NEG_BIG);

#pragma unroll
            for (int i = 0; i < 5; ++i) np[i] = npn[i];
            gE = gEn; gO1 = gO1n; gO2 = gO2n;
        }

        // final: res2[s] = np2[s] + g2[127][s]
        res_sh[sB + 0] = np[0] + gE;
        res_sh[sB + 1] = np[1] + gO1;
        res_sh[sB + 2] = np[2] + gE;
        res_sh[sB + 3] = np[3] + gO2;
        if (lane == 31) res_sh[128] = np[4] + gE;
        __syncwarp();

        if (lane == 0) {
            const int   L  = 2 * tlen[n] + 1;
            const float l2 = lse3_2(res_sh[L - 1], res_sh[L - 2], NEG_BIG);
            out[n] = -((LN2 * l2) / (float)tlen[n]);
        }
    }
}

} // anonymous namespace

extern "C" void kernel_launch(void* const* d_in, const int* /*in_sizes*/, int /*n_in*/,
                              void* d_out, int /*out_size*/) {
    const float* mask     = (const float*)d_in[0];
    const float* classify = (const float*)d_in[1];
    const int*   targets  = (const int*)d_in[2];
    // d_in[3] = input_lengths (always T, unused)
    const int*   tlen     = (const int*)d_in[4];

    fused_kernel<<<N_, 512>>>(mask, classify, targets, tlen, (float*)d_out);
}